// round 2
// baseline (speedup 1.0000x reference)
#include <cuda_runtime.h>
#include <cstdint>
#include <cstddef>

// Sinkhorn factored form: y = diag(r) * A * diag(c),  A = exp(x)+eps constant.
//   r <- 1/(A c);  c <- 1/(A^T r)
// 16 matrices of 512x512 fp32; one 8-CTA cluster per matrix; A register-resident.
// R2: 512 threads/CTA (16 warps) for latency hiding + packed f32x2 FMA.

#define N_ITERS 100
#define NDIM 512

__device__ __forceinline__ uint32_t smem_u32(const void* p) {
    return (uint32_t)__cvta_generic_to_shared(p);
}
__device__ __forceinline__ uint32_t mapa_u32(uint32_t addr, uint32_t rank) {
    uint32_t r;
    asm("mapa.shared::cluster.u32 %0, %1, %2;" : "=r"(r) : "r"(addr), "r"(rank));
    return r;
}
__device__ __forceinline__ void st_cluster_f32(uint32_t addr, float v) {
    asm volatile("st.shared::cluster.f32 [%0], %1;"
                 :: "r"(addr), "f"(v) : "memory");
}
__device__ __forceinline__ void fma2(uint64_t& d, uint64_t a, uint64_t b, uint64_t c) {
    asm("fma.rn.f32x2 %0, %1, %2, %3;" : "=l"(d) : "l"(a), "l"(b), "l"(c));
}
__device__ __forceinline__ uint64_t pack2(float lo, float hi) {
    uint64_t r;
    asm("mov.b64 %0, {%1, %2};" : "=l"(r) : "f"(lo), "f"(hi));
    return r;
}
__device__ __forceinline__ void unpack2(float& lo, float& hi, uint64_t v) {
    asm("mov.b64 {%0, %1}, %2;" : "=f"(lo), "=f"(hi) : "l"(v));
}
#define CLUSTER_SYNC() do { \
    asm volatile("barrier.cluster.arrive.aligned;" ::: "memory"); \
    asm volatile("barrier.cluster.wait.aligned;"   ::: "memory"); } while (0)

__global__ void __launch_bounds__(512, 1) __cluster_dims__(8, 1, 1)
sinkhorn_kernel(const float* __restrict__ x, float* __restrict__ out)
{
    __shared__ __align__(16) float c_smem[NDIM];      // column scaling c
    __shared__ __align__(16) float part[16][NDIM];    // per-warp column partials
    __shared__ __align__(16) float peer_part[8][64];  // incoming per-CTA partials

    const int tid  = threadIdx.x;
    const int warp = tid >> 5;            // 0..15
    const int lane = tid & 31;
    const int rank = blockIdx.x & 7;      // CTA rank in cluster = row block
    const int bmat = blockIdx.x >> 3;     // matrix index 0..15

    const int row0 = rank * 64 + warp * 4;      // 4 rows per warp
    // Thread owns column pairs: cols = 64*q2 + 2*lane + {0,1}, q2 = 0..7

    // ---------------- Prologue: A = exp(x) + eps, packed f32x2 in regs -------
    uint64_t a2[4][8];
    const float* xbase = x + ((size_t)bmat * NDIM + row0) * NDIM;
    #pragma unroll
    for (int p = 0; p < 4; p++) {
        const float2* xrow = (const float2*)(xbase + (size_t)p * NDIM) + lane;
        #pragma unroll
        for (int q = 0; q < 8; q++) {
            float2 v = xrow[32 * q];
            a2[p][q] = pack2(expf(v.x) + 0.001f, expf(v.y) + 0.001f);
        }
    }

    c_smem[tid] = 1.0f;     // 512 threads init all 512 entries
    __syncthreads();

    const uint32_t peer_base = smem_u32(&peer_part[0][0]);
    const uint32_t c_base    = smem_u32(&c_smem[0]);
    const uint64_t* c2       = (const uint64_t*)c_smem;

    float r[4];

    for (int it = 0; it < N_ITERS; it++) {
        // ---- step 1: row sums acc_i = (A c)_i ; r = 1/acc  (CTA-local) ----
        uint64_t acc2[4];
        #pragma unroll
        for (int p = 0; p < 4; p++) acc2[p] = 0ull;   // (0.0f, 0.0f)
        #pragma unroll
        for (int q = 0; q < 8; q++) {
            uint64_t cq = c2[32 * q + lane];
            #pragma unroll
            for (int p = 0; p < 4; p++) fma2(acc2[p], a2[p][q], cq, acc2[p]);
        }
        float acc[4];
        #pragma unroll
        for (int p = 0; p < 4; p++) {
            float lo, hi; unpack2(lo, hi, acc2[p]);
            acc[p] = lo + hi;
        }
        #pragma unroll
        for (int off = 16; off > 0; off >>= 1) {
            #pragma unroll
            for (int p = 0; p < 4; p++)
                acc[p] += __shfl_xor_sync(0xffffffffu, acc[p], off);
        }
        #pragma unroll
        for (int p = 0; p < 4; p++) r[p] = 1.0f / acc[p];

        // ---- step 2: column partials sum_i r_i A_ij over this warp's rows ----
        uint64_t r2[4];
        #pragma unroll
        for (int p = 0; p < 4; p++) r2[p] = pack2(r[p], r[p]);
        uint64_t* prow = (uint64_t*)&part[warp][0];
        #pragma unroll
        for (int q = 0; q < 8; q++) {
            uint64_t s2 = 0ull;
            #pragma unroll
            for (int p = 0; p < 4; p++) fma2(s2, r2[p], a2[p][q], s2);
            prow[32 * q + lane] = s2;
        }
        __syncthreads();

        // ---- step 3: reduce 16 warps, push to owning CTA (1 col per thread) --
        {
            float s = 0.0f;
            #pragma unroll
            for (int w = 0; w < 16; w++) s += part[w][tid];
            int owner = tid >> 6;
            uint32_t dst = mapa_u32(
                peer_base + (uint32_t)((rank * 64 + (tid & 63)) * sizeof(float)),
                (uint32_t)owner);
            st_cluster_f32(dst, s);
        }
        CLUSTER_SYNC();

        // ---- step 4: owner reduces 8 CTA partials, broadcasts c -------------
        if (tid < 64) {
            float s = 0.0f;
            #pragma unroll
            for (int rr = 0; rr < 8; rr++) s += peer_part[rr][tid];
            float cj = 1.0f / s;
            uint32_t off = (uint32_t)((rank * 64 + tid) * sizeof(float));
            #pragma unroll
            for (int rk = 0; rk < 8; rk++)
                st_cluster_f32(mapa_u32(c_base + off, (uint32_t)rk), cj);
        }
        CLUSTER_SYNC();
    }

    // ---------------- Epilogue: y_ij = r_i * A_ij * c_j ----------------------
    float* obase = out + ((size_t)bmat * NDIM + row0) * NDIM;
    #pragma unroll
    for (int p = 0; p < 4; p++) {
        float2* orow = (float2*)(obase + (size_t)p * NDIM) + lane;
        #pragma unroll
        for (int q = 0; q < 8; q++) {
            float alo, ahi; unpack2(alo, ahi, a2[p][q]);
            float2 cv = ((const float2*)c_smem)[32 * q + lane];
            float2 o;
            o.x = r[p] * alo * cv.x;
            o.y = r[p] * ahi * cv.y;
            orow[32 * q] = o;
        }
    }
}

extern "C" void kernel_launch(void* const* d_in, const int* in_sizes, int n_in,
                              void* d_out, int out_size)
{
    (void)in_sizes; (void)n_in; (void)out_size;
    const float* x = (const float*)d_in[0];
    float* out = (float*)d_out;
    // 16 matrices * 8 CTAs = 128 CTAs; __cluster_dims__(8) groups them per matrix.
    sinkhorn_kernel<<<128, 512>>>(x, out);
}

// round 4
// speedup vs baseline: 1.3801x; 1.3801x over previous
#include <cuda_runtime.h>
#include <cstdint>
#include <cstddef>

// Sinkhorn factored form: y = diag(r) * A * diag(c),  A = exp(x)+eps constant.
//   r <- 1/(A c);  c <- 1/(A^T r)
// 16 matrices of 512x512 fp32; one 8-CTA cluster per matrix; A register-resident.
// R4: zero cluster barriers in the loop — point-to-point st.async + mbarrier
//     transaction tracking. (redux.f32 unsupported on sm_103 -> shfl butterfly.)

#define N_ITERS 100
#define NDIM 512

__device__ __forceinline__ uint32_t smem_u32(const void* p) {
    return (uint32_t)__cvta_generic_to_shared(p);
}
__device__ __forceinline__ uint32_t mapa_u32(uint32_t addr, uint32_t rank) {
    uint32_t r;
    asm("mapa.shared::cluster.u32 %0, %1, %2;" : "=r"(r) : "r"(addr), "r"(rank));
    return r;
}
__device__ __forceinline__ void fma2(uint64_t& d, uint64_t a, uint64_t b, uint64_t c) {
    asm("fma.rn.f32x2 %0, %1, %2, %3;" : "=l"(d) : "l"(a), "l"(b), "l"(c));
}
__device__ __forceinline__ uint64_t pack2(float lo, float hi) {
    uint64_t r;
    asm("mov.b64 %0, {%1, %2};" : "=l"(r) : "f"(lo), "f"(hi));
    return r;
}
__device__ __forceinline__ void unpack2(float& lo, float& hi, uint64_t v) {
    asm("mov.b64 {%0, %1}, %2;" : "=f"(lo), "=f"(hi) : "l"(v));
}
// async store into (possibly remote) cluster smem, tx-counted on that CTA's mbarrier
__device__ __forceinline__ void st_async_f32(uint32_t dst, float v, uint32_t mbar) {
    asm volatile(
        "st.async.shared::cluster.mbarrier::complete_tx::bytes.b32 [%0], %1, [%2];"
        :: "r"(dst), "r"(__float_as_uint(v)), "r"(mbar) : "memory");
}
__device__ __forceinline__ void mbar_init(uint32_t addr, uint32_t cnt) {
    asm volatile("mbarrier.init.shared.b64 [%0], %1;" :: "r"(addr), "r"(cnt) : "memory");
}
__device__ __forceinline__ void mbar_expect_tx(uint32_t addr, uint32_t bytes) {
    asm volatile("mbarrier.arrive.expect_tx.shared.b64 _, [%0], %1;"
                 :: "r"(addr), "r"(bytes) : "memory");
}
__device__ __forceinline__ void mbar_wait_cluster(uint32_t addr, uint32_t parity) {
    uint32_t done = 0;
    while (!done) {
        asm volatile(
            "{\n\t.reg .pred p;\n\t"
            "mbarrier.try_wait.parity.acquire.cluster.shared::cta.b64 p, [%1], %2, 0x989680;\n\t"
            "selp.b32 %0, 1, 0, p;\n\t}"
            : "=r"(done) : "r"(addr), "r"(parity) : "memory");
    }
}
#define CLUSTER_SYNC() do { \
    asm volatile("barrier.cluster.arrive.aligned;" ::: "memory"); \
    asm volatile("barrier.cluster.wait.aligned;"   ::: "memory"); } while (0)

__global__ void __launch_bounds__(512, 1) __cluster_dims__(8, 1, 1)
sinkhorn_kernel(const float* __restrict__ x, float* __restrict__ out)
{
    __shared__ __align__(16) float c_smem[NDIM];      // column scaling c
    __shared__ __align__(16) float part[16][NDIM];    // per-warp column partials
    __shared__ __align__(16) float peer_part[8][64];  // per-CTA partials for owned cols
    __shared__ __align__(8)  uint64_t mbars[2];       // [0]=part_mbar, [1]=c_mbar

    const int tid  = threadIdx.x;
    const int warp = tid >> 5;            // 0..15
    const int lane = tid & 31;
    const int rank = blockIdx.x & 7;      // CTA rank in cluster = row block
    const int bmat = blockIdx.x >> 3;     // matrix index 0..15

    const int row0 = rank * 64 + warp * 4;      // 4 rows per warp

    // ---------------- Prologue: A = exp(x) + eps, packed f32x2 in regs -------
    uint64_t a2[4][8];
    const float* xbase = x + ((size_t)bmat * NDIM + row0) * NDIM;
    #pragma unroll
    for (int p = 0; p < 4; p++) {
        const float2* xrow = (const float2*)(xbase + (size_t)p * NDIM) + lane;
        #pragma unroll
        for (int q = 0; q < 8; q++) {
            float2 v = xrow[32 * q];
            a2[p][q] = pack2(expf(v.x) + 0.001f, expf(v.y) + 0.001f);
        }
    }

    const uint32_t peer_base = smem_u32(&peer_part[0][0]);
    const uint32_t c_base    = smem_u32(&c_smem[0]);
    const uint32_t pm_addr   = smem_u32(&mbars[0]);
    const uint32_t cm_addr   = smem_u32(&mbars[1]);

    c_smem[tid] = 1.0f;
    if (tid == 0) {
        mbar_init(pm_addr, 1);
        mbar_init(cm_addr, 1);
        mbar_expect_tx(pm_addr, NDIM * 4);   // arm phase 0
        mbar_expect_tx(cm_addr, NDIM * 4);
    }
    __syncthreads();
    CLUSTER_SYNC();   // all barriers live + armed before any st.async

    // loop-invariant partial-store destination (column owner = tid>>6)
    const uint32_t own      = (uint32_t)(tid >> 6);
    const uint32_t p_dst    = mapa_u32(peer_base + (uint32_t)((rank * 64 + (tid & 63)) * 4), own);
    const uint32_t p_mbar_r = mapa_u32(pm_addr, own);

    const uint64_t* c2 = (const uint64_t*)c_smem;
    float r[4];

    for (int it = 0; it < N_ITERS; it++) {
        const uint32_t parity = (uint32_t)(it & 1);

        // ---- step 1: row sums acc_i = (A c)_i ; r = 1/acc  (CTA-local) ----
        uint64_t acc2[4];
        #pragma unroll
        for (int p = 0; p < 4; p++) acc2[p] = 0ull;
        #pragma unroll
        for (int q = 0; q < 8; q++) {
            uint64_t cq = c2[32 * q + lane];
            #pragma unroll
            for (int p = 0; p < 4; p++) fma2(acc2[p], a2[p][q], cq, acc2[p]);
        }
        float acc[4];
        #pragma unroll
        for (int p = 0; p < 4; p++) {
            float lo, hi; unpack2(lo, hi, acc2[p]);
            acc[p] = lo + hi;
        }
        #pragma unroll
        for (int off = 16; off > 0; off >>= 1) {
            #pragma unroll
            for (int p = 0; p < 4; p++)
                acc[p] += __shfl_xor_sync(0xffffffffu, acc[p], off);
        }
        #pragma unroll
        for (int p = 0; p < 4; p++) r[p] = 1.0f / acc[p];

        // ---- step 2: column partials sum_i r_i A_ij over this warp's rows ----
        uint64_t r2[4];
        #pragma unroll
        for (int p = 0; p < 4; p++) r2[p] = pack2(r[p], r[p]);
        uint64_t* prow = (uint64_t*)&part[warp][0];
        #pragma unroll
        for (int q = 0; q < 8; q++) {
            uint64_t s2 = 0ull;
            #pragma unroll
            for (int p = 0; p < 4; p++) fma2(s2, r2[p], a2[p][q], s2);
            prow[32 * q + lane] = s2;
        }
        __syncthreads();

        // ---- step 3: reduce 16 warps, async-send to owning CTA --------------
        {
            float s = 0.0f;
            #pragma unroll
            for (int w = 0; w < 16; w++) s += part[w][tid];
            st_async_f32(p_dst, s, p_mbar_r);
        }

        // ---- step 4 (owner role, tid<64): gather partials, compute & send c --
        if (tid < 64) {
            mbar_wait_cluster(pm_addr, parity);
            if (tid == 0) mbar_expect_tx(pm_addr, NDIM * 4);  // re-arm BEFORE c send
            float s = 0.0f;
            #pragma unroll
            for (int rr = 0; rr < 8; rr++) s += peer_part[rr][tid];
            float cj = 1.0f / s;
            uint32_t off = (uint32_t)((rank * 64 + tid) * 4);
            #pragma unroll
            for (int rk = 0; rk < 8; rk++)
                st_async_f32(mapa_u32(c_base + off, (uint32_t)rk), cj,
                             mapa_u32(cm_addr, (uint32_t)rk));
        }

        // ---- step 5: everyone waits for the full new c -----------------------
        mbar_wait_cluster(cm_addr, parity);
        if (tid == 0) mbar_expect_tx(cm_addr, NDIM * 4);  // re-arm (gated by next
        // iteration's __syncthreads before any of our step-3 sends)
    }

    CLUSTER_SYNC();   // all in-flight remote traffic accounted before smem teardown

    // ---------------- Epilogue: y_ij = r_i * A_ij * c_j ----------------------
    float* obase = out + ((size_t)bmat * NDIM + row0) * NDIM;
    #pragma unroll
    for (int p = 0; p < 4; p++) {
        float2* orow = (float2*)(obase + (size_t)p * NDIM) + lane;
        #pragma unroll
        for (int q = 0; q < 8; q++) {
            float alo, ahi; unpack2(alo, ahi, a2[p][q]);
            float2 cv = ((const float2*)c_smem)[32 * q + lane];
            float2 o;
            o.x = r[p] * alo * cv.x;
            o.y = r[p] * ahi * cv.y;
            orow[32 * q] = o;
        }
    }
}

extern "C" void kernel_launch(void* const* d_in, const int* in_sizes, int n_in,
                              void* d_out, int out_size)
{
    (void)in_sizes; (void)n_in; (void)out_size;
    const float* x = (const float*)d_in[0];
    float* out = (float*)d_out;
    // 16 matrices * 8 CTAs = 128 CTAs; __cluster_dims__(8) groups them per matrix.
    sinkhorn_kernel<<<128, 512>>>(x, out);
}